// round 1
// baseline (speedup 1.0000x reference)
#include <cuda_runtime.h>
#include <cuda_bf16.h>

// MLPAttention: B=4, N=512, KLEN=512, D=64, TAU=4
//   Wq = W1[0::2], Wk = W1[1::2]
//   hq = Q@Wq + b1 (b1 folded), hk = K@Wk
//   res[n,k] = sum_d relu(hq[n,d]+hk[k,d]) * W2[d]   (b2 cancels in softmax)
//   att = softmax(res/TAU), out = att@V
// Outputs concatenated: out (B*N*D floats) then att (B*N*K floats).

#define BB 4
#define NN 512
#define KL 512
#define DD 64

// scratch (allocation-free rule: __device__ globals)
__device__ float g_hq[BB * NN * DD];        // [row][e]
__device__ float g_hkT[BB * DD * KL];       // [b][e][k]  (transposed for coalesced k-loads)

// ---------- packed f32x2 helpers (sm_103a) ----------
__device__ __forceinline__ unsigned long long pk2(float x, float y) {
    unsigned long long r;
    asm("mov.b64 %0, {%1, %2};" : "=l"(r) : "f"(x), "f"(y));
    return r;
}
__device__ __forceinline__ float2 up2(unsigned long long u) {
    float2 f;
    asm("mov.b64 {%0, %1}, %2;" : "=f"(f.x), "=f"(f.y) : "l"(u));
    return f;
}
__device__ __forceinline__ unsigned long long fadd2(unsigned long long a, unsigned long long b) {
    unsigned long long r;
    asm("add.rn.f32x2 %0, %1, %2;" : "=l"(r) : "l"(a), "l"(b));
    return r;
}
__device__ __forceinline__ unsigned long long ffma2(unsigned long long a, unsigned long long b,
                                                    unsigned long long c) {
    unsigned long long r;
    asm("fma.rn.f32x2 %0, %1, %2, %3;" : "=l"(r) : "l"(a), "l"(b), "l"(c));
    return r;
}

// ---------- Kernel A1: hq = Q@Wq + b1 ----------
// 4 rows per block, 256 threads: thread t -> (row_local = t/64, e = t%64)
__global__ __launch_bounds__(256) void kA1(const float* __restrict__ Q,
                                           const float* __restrict__ W1,
                                           const float* __restrict__ b1,
                                           float* __restrict__ hq) {
    __shared__ float Qs[4 * 64];
    int r0 = blockIdx.x * 4;
    int t = threadIdx.x;
    Qs[t] = Q[r0 * 64 + t];
    __syncthreads();
    int rl = t >> 6, e = t & 63;
    float acc = b1[e];
#pragma unroll
    for (int d = 0; d < 64; d++)
        acc = fmaf(Qs[rl * 64 + d], __ldg(&W1[d * 128 + e]), acc);  // W1[2d][e]
    hq[(r0 + rl) * 64 + e] = acc;
}

// ---------- Kernel A2: hkT[b][e][k] = (K@Wk)[k][e] ----------
// grid 512: bid -> b (4) x ktile(8, 64 k each) x etile(16, 4 e each)
__global__ __launch_bounds__(256) void kA2(const float* __restrict__ K,
                                           const float* __restrict__ W1,
                                           float* __restrict__ hkT) {
    __shared__ float Ks[64 * 65];
    int bid = blockIdx.x;
    int b = bid >> 7;
    int kt = (bid >> 4) & 7;
    int et = bid & 15;
    int t = threadIdx.x;
#pragma unroll
    for (int j = 0; j < 16; j++) {
        int idx = t + 256 * j;
        int kk = idx >> 6, d = idx & 63;
        Ks[kk * 65 + d] = K[(b * 512 + kt * 64 + kk) * 64 + d];
    }
    __syncthreads();
    int el = t >> 6, kl = t & 63;
    int e = et * 4 + el;
    float acc = 0.f;
#pragma unroll
    for (int d = 0; d < 64; d++)
        acc = fmaf(Ks[kl * 65 + d], __ldg(&W1[d * 128 + 64 + e]), acc);  // W1[2d+1][e]
    hkT[b * (64 * 512) + e * 512 + kt * 64 + kl] = acc;  // coalesced over kl
}

// ---------- Kernel B: res + softmax -> att ----------
// grid 128 (b x 32 n-tiles of 16), 512 threads. thread = one k column.
// hk row lives as one LDG per e (coalesced, reused 16x). hq as packed n-pairs in smem.
__global__ __launch_bounds__(512) void kB(const float* __restrict__ hq,
                                          const float* __restrict__ hkT,
                                          const float* __restrict__ W2,
                                          float* __restrict__ att) {
    __shared__ __align__(8) float hq_f[64 * 16];   // [e][i] i = n-local
    __shared__ unsigned long long w2s[64];         // {w2[e], w2[e]}
    __shared__ float res_s[16 * 512];

    int b = blockIdx.x >> 5;
    int n0 = (blockIdx.x & 31) << 4;
    int t = threadIdx.x;

    {   // stage hq tile (two coalesced loads per thread)
        int i = t >> 6, e = t & 63;
        hq_f[e * 16 + i]     = hq[(b * 512 + n0 + i) * 64 + e];
        hq_f[e * 16 + i + 8] = hq[(b * 512 + n0 + i + 8) * 64 + e];
    }
    if (t < 64) { float w = W2[t]; w2s[t] = pk2(w, w); }
    __syncthreads();

    const unsigned long long* hq2 = (const unsigned long long*)hq_f;  // [e][p] p=n-pair
    const float* hkb = hkT + b * (64 * 512) + t;

    unsigned long long acc[8];
#pragma unroll
    for (int p = 0; p < 8; p++) acc[p] = 0ull;  // bitpattern 0 == {0.f,0.f}

#pragma unroll 8
    for (int e = 0; e < 64; e++) {
        float hkv = hkb[e * 512];                      // coalesced LDG (L2-resident)
        unsigned long long hk2 = pk2(hkv, hkv);
        unsigned long long w2e = w2s[e];               // broadcast LDS.64
#pragma unroll
        for (int p = 0; p < 8; p++) {
            unsigned long long s = fadd2(hq2[e * 8 + p], hk2);  // packed add
            float2 sf = up2(s);
            float2 r2;
            r2.x = fmaxf(sf.x, 0.f);
            r2.y = fmaxf(sf.y, 0.f);
            acc[p] = ffma2(pk2(r2.x, r2.y), w2e, acc[p]);       // packed fma
        }
    }
#pragma unroll
    for (int p = 0; p < 8; p++) {
        float2 a = up2(acc[p]);
        res_s[(2 * p) * 512 + t] = a.x;
        res_s[(2 * p + 1) * 512 + t] = a.y;
    }
    __syncthreads();

    // softmax: warp w owns row n0+w (16 warps, 16 rows)
    int w = t >> 5, lane = t & 31;
    float v[16], m = -1e30f;
#pragma unroll
    for (int i = 0; i < 16; i++) {
        v[i] = res_s[w * 512 + lane + 32 * i];
        m = fmaxf(m, v[i]);
    }
#pragma unroll
    for (int o = 16; o; o >>= 1) m = fmaxf(m, __shfl_xor_sync(0xffffffffu, m, o));
    float s = 0.f;
#pragma unroll
    for (int i = 0; i < 16; i++) {
        v[i] = __expf((v[i] - m) * 0.25f);  // /TAU
        s += v[i];
    }
#pragma unroll
    for (int o = 16; o; o >>= 1) s += __shfl_xor_sync(0xffffffffu, s, o);
    float inv = 1.f / s;
    float* ap = att + (b * 512 + n0 + w) * 512 + lane;
#pragma unroll
    for (int i = 0; i < 16; i++) ap[32 * i] = v[i] * inv;
}

// ---------- Kernel C: out = att @ V ----------
// grid 128 (b x 32 n-tiles of 16), 256 threads, smem-tiled over K (4 tiles of 128).
// thread -> (d-pair d2 = t%32, n-group ng = t/32 owning rows 2ng, 2ng+1)
__global__ __launch_bounds__(256) void kC(const float* __restrict__ att,
                                          const float* __restrict__ V,
                                          float* __restrict__ out) {
    __shared__ float att_s[16 * 128];
    __shared__ __align__(8) float Vs[128 * 64];
    int b = blockIdx.x >> 5;
    int n0 = (blockIdx.x & 31) << 4;
    int t = threadIdx.x;
    int d2 = t & 31, ng = t >> 5;
    float2 acc0 = {0.f, 0.f}, acc1 = {0.f, 0.f};

    for (int kt = 0; kt < 4; kt++) {
        __syncthreads();
#pragma unroll
        for (int j = 0; j < 8; j++) {
            int idx = t + 256 * j;
            att_s[idx] = att[(b * 512 + n0 + (idx >> 7)) * 512 + kt * 128 + (idx & 127)];
        }
#pragma unroll
        for (int j = 0; j < 32; j++) {
            int idx = t + 256 * j;
            Vs[idx] = V[(b * 512 + kt * 128 + (idx >> 6)) * 64 + (idx & 63)];
        }
        __syncthreads();
        const float2* V2 = (const float2*)Vs;
#pragma unroll 8
        for (int kk = 0; kk < 128; kk++) {
            float2 vv = V2[kk * 32 + d2];
            float a0 = att_s[(ng * 2) * 128 + kk];
            float a1 = att_s[(ng * 2 + 1) * 128 + kk];
            acc0.x = fmaf(a0, vv.x, acc0.x);
            acc0.y = fmaf(a0, vv.y, acc0.y);
            acc1.x = fmaf(a1, vv.x, acc1.x);
            acc1.y = fmaf(a1, vv.y, acc1.y);
        }
    }
    int n = n0 + ng * 2;
    float2* o2 = (float2*)out;
    o2[(b * 512 + n) * 32 + d2] = acc0;
    o2[(b * 512 + n + 1) * 32 + d2] = acc1;
}

extern "C" void kernel_launch(void* const* d_in, const int* in_sizes, int n_in,
                              void* d_out, int out_size) {
    const float* Q  = (const float*)d_in[0];
    const float* K  = (const float*)d_in[1];
    const float* V  = (const float*)d_in[2];
    const float* W1 = (const float*)d_in[3];
    const float* b1 = (const float*)d_in[4];
    const float* W2 = (const float*)d_in[5];
    // b2 (d_in[6]) cancels in softmax and never reaches an output.

    float* out = (float*)d_out;                       // B*N*D
    float* att = (float*)d_out + BB * NN * DD;        // B*N*KL

    float* hq;  cudaGetSymbolAddress((void**)&hq,  g_hq);
    float* hkT; cudaGetSymbolAddress((void**)&hkT, g_hkT);

    kA1<<<512, 256>>>(Q, W1, b1, hq);
    kA2<<<512, 256>>>(K, W1, hkT);
    kB<<<128, 512>>>(hq, hkT, W2, att);
    kC<<<128, 256>>>(att, V, out);
}